// round 10
// baseline (speedup 1.0000x reference)
#include <cuda_runtime.h>
#include <cstdint>

namespace {
constexpr int  CIN  = 16;
constexpr int  COUT = 16;
constexpr int  KS   = 4;
constexpr long long NN = 524288;
constexpr int  THREADS = 128;                 // 4 warps
constexpr int  TOK     = 128;                 // tokens per CTA-iter
constexpr int  TILES   = (int)(8 * NN / TOK); // 32768
constexpr int  GRID    = 8192;                // 4 tiles per CTA
constexpr int  PADT    = 132;                 // staging row pitch (floats)
}

__device__ __forceinline__ unsigned long long mul2(unsigned long long a,
                                                   unsigned long long b) {
    unsigned long long d;
    asm("mul.rn.f32x2 %0, %1, %2;" : "=l"(d) : "l"(a), "l"(b));
    return d;
}
__device__ __forceinline__ unsigned long long pack2(float lo, float hi) {
    unsigned long long d;
    asm("mov.b64 %0, {%1, %2};" : "=l"(d) : "f"(lo), "f"(hi));
    return d;
}
__device__ __forceinline__ uint32_t packbf(float hi, float lo) {
    uint32_t r;
    asm("cvt.rn.bf16x2.f32 %0, %1, %2;" : "=r"(r) : "f"(hi), "f"(lo));
    return r;
}
__device__ __forceinline__ void mma_bf16(float* d, const uint32_t* a,
                                         uint32_t b0, uint32_t b1) {
    asm volatile(
        "mma.sync.aligned.m16n8k16.row.col.f32.bf16.bf16.f32 "
        "{%0,%1,%2,%3}, {%4,%5,%6,%7}, {%8,%9}, {%0,%1,%2,%3};"
        : "+f"(d[0]), "+f"(d[1]), "+f"(d[2]), "+f"(d[3])
        : "r"(a[0]), "r"(a[1]), "r"(a[2]), "r"(a[3]), "r"(b0), "r"(b1));
}
__device__ __forceinline__ void split_z(unsigned long long z,
                                        uint32_t& zh, uint32_t& zl) {
    float z0 = __uint_as_float((uint32_t)z);
    float z1 = __uint_as_float((uint32_t)(z >> 32));
    zh = packbf(z1, z0);
    float h0 = __uint_as_float(zh << 16);
    float h1 = __uint_as_float(zh & 0xFFFF0000u);
    zl = packbf(z1 - h1, z0 - h0);
}

__global__ __launch_bounds__(THREADS)
void tconv_mma_kernel(const float* __restrict__ inp,   // [B, CIN, N]
                      const float* __restrict__ wgt,   // [COUT, KS, CIN]
                      const float* __restrict__ att,   // [B, KS, N]
                      float* __restrict__ out)         // [B, COUT, N]
{
    __shared__ __align__(16) float xs[2][CIN * PADT];
    __shared__ __align__(16) float ss[2][KS * PADT];

    const int tid  = threadIdx.x;
    const int lane = tid & 31;
    const int w    = tid >> 5;
    const int cq   = lane & 3;
    const int r    = lane >> 2;
    const int c0   = tid >> 5;
    const int q    = lane;

    // W as A-fragments (built once, split hi/lo)
    uint32_t ah[KS][4], al[KS][4];
    #pragma unroll
    for (int kt = 0; kt < KS; kt++) {
        #pragma unroll
        for (int idx = 0; idx < 4; idx++) {
            int o  = r + 8 * (idx & 1);
            int cb = 2 * cq + 8 * (idx >> 1);
            float wa = wgt[(o * KS + kt) * CIN + cb];
            float wb = wgt[(o * KS + kt) * CIN + cb + 1];
            uint32_t hp = packbf(wb, wa);
            float ha = __uint_as_float(hp << 16);
            float hb = __uint_as_float(hp & 0xFFFF0000u);
            ah[kt][idx] = hp;
            al[kt][idx] = packbf(wb - hb, wa - ha);
        }
    }

    // prologue: vectorized load of tile 0
    float4 rx[4], rs;
    {
        int t = blockIdx.x;
        long long b = t >> 12, n = ((long long)(t & 4095) << 7) + 4 * q;
        #pragma unroll
        for (int cc = 0; cc < 4; cc++)
            rx[cc] = *reinterpret_cast<const float4*>(inp + (b * CIN + cc * 4 + c0) * NN + n);
        rs = *reinterpret_cast<const float4*>(att + (b * KS + c0) * NN + n);
    }

    for (int i = 0; i < TILES / GRID; i++) {
        const int t = blockIdx.x + i * GRID;
        const int p = i & 1;
        float* xb = xs[p];
        float* sb = ss[p];

        #pragma unroll
        for (int cc = 0; cc < 4; cc++)
            *reinterpret_cast<float4*>(xb + (cc * 4 + c0) * PADT + 4 * q) = rx[cc];
        *reinterpret_cast<float4*>(sb + c0 * PADT + 4 * q) = rs;

        if (i + 1 < TILES / GRID) {
            int tn = t + GRID;
            long long b = tn >> 12, n = ((long long)(tn & 4095) << 7) + 4 * q;
            #pragma unroll
            for (int cc = 0; cc < 4; cc++)
                rx[cc] = *reinterpret_cast<const float4*>(inp + (b * CIN + cc * 4 + c0) * NN + n);
            rs = *reinterpret_cast<const float4*>(att + (b * KS + c0) * NN + n);
        }
        __syncthreads();

        const long long bb = t >> 12;
        const long long n0 = ((long long)(t & 4095) << 7);
        float* ob = out + bb * COUT * NN + n0;

        #pragma unroll
        for (int jp = 0; jp < 2; jp++) {
            const int tb0 = w * 32 + jp * 16;
            const int tb1 = tb0 + 8;
            const int tA = tb0 + r, tB = tb1 + r;

            unsigned long long xA0 = pack2(xb[(2*cq)   * PADT + tA], xb[(2*cq+1) * PADT + tA]);
            unsigned long long xA1 = pack2(xb[(2*cq+8) * PADT + tA], xb[(2*cq+9) * PADT + tA]);
            unsigned long long xB0 = pack2(xb[(2*cq)   * PADT + tB], xb[(2*cq+1) * PADT + tB]);
            unsigned long long xB1 = pack2(xb[(2*cq+8) * PADT + tB], xb[(2*cq+9) * PADT + tB]);

            float dA[4] = {0.f, 0.f, 0.f, 0.f};
            float dB[4] = {0.f, 0.f, 0.f, 0.f};

            #pragma unroll
            for (int kt = 0; kt < KS; kt++) {
                float sa = sb[kt * PADT + tA];
                float sv = sb[kt * PADT + tB];
                unsigned long long sda = pack2(sa, sa);
                unsigned long long sdb = pack2(sv, sv);

                uint32_t bA0h, bA0l, bA1h, bA1l, bB0h, bB0l, bB1h, bB1l;
                split_z(mul2(xA0, sda), bA0h, bA0l);
                split_z(mul2(xA1, sda), bA1h, bA1l);
                split_z(mul2(xB0, sdb), bB0h, bB0l);
                split_z(mul2(xB1, sdb), bB1h, bB1l);

                mma_bf16(dA, ah[kt], bA0h, bA1h);
                mma_bf16(dB, ah[kt], bB0h, bB1h);
                mma_bf16(dA, ah[kt], bA0l, bA1l);
                mma_bf16(dB, ah[kt], bB0l, bB1l);
                mma_bf16(dA, al[kt], bA0h, bA1h);
                mma_bf16(dB, al[kt], bB0h, bB1h);
            }

            // ---- shuffle-transposed stores: per row, lanes compose float4 of
            // 4 consecutive tokens; 2 STG.128 per jp instead of 4 scattered STG.64.
            // xor-1 partner exchange within the 4-lane cq group.
            const unsigned FULL = 0xFFFFFFFFu;
            float eA0 = __shfl_xor_sync(FULL, dA[0], 1);
            float eA1 = __shfl_xor_sync(FULL, dA[1], 1);
            float eB0 = __shfl_xor_sync(FULL, dB[0], 1);
            float eB1 = __shfl_xor_sync(FULL, dB[1], 1);
            float eA2 = __shfl_xor_sync(FULL, dA[2], 1);
            float eA3 = __shfl_xor_sync(FULL, dA[3], 1);
            float eB2 = __shfl_xor_sync(FULL, dB[2], 1);
            float eB3 = __shfl_xor_sync(FULL, dB[3], 1);

            // token offset within the 16-token span covered by this jp:
            // even cq -> A-chunk at 4*(cq>>1); odd cq -> B-chunk at 8 + 4*(cq>>1)
            const int off = ((cq & 1) << 3) | ((cq >> 1) << 2);
            float4 v0, v1;
            if ((cq & 1) == 0) {
                v0 = make_float4(dA[0], dA[1], eA0, eA1);   // row r,   tokens tb0+off..+3
                v1 = make_float4(dA[2], dA[3], eA2, eA3);   // row r+8
            } else {
                v0 = make_float4(eB0, eB1, dB[0], dB[1]);   // row r,   tokens tb0+off..+3
                v1 = make_float4(eB2, eB3, dB[2], dB[3]);   // row r+8
            }
            *reinterpret_cast<float4*>(ob + (long long)r       * NN + tb0 + off) = v0;
            *reinterpret_cast<float4*>(ob + (long long)(r + 8) * NN + tb0 + off) = v1;
        }
    }
}

extern "C" void kernel_launch(void* const* d_in, const int* in_sizes, int n_in,
                              void* d_out, int out_size)
{
    const float* inp = (const float*)d_in[0];   // input  [8,16,524288]
    const float* wgt = (const float*)d_in[1];   // weight [16,4,16]
    const float* att = (const float*)d_in[2];   // attention_score [8,4,524288]
    float* out = (float*)d_out;                 // [8,16,524288]

    tconv_mma_kernel<<<GRID, THREADS>>>(inp, wgt, att, out);
}

// round 11
// speedup vs baseline: 1.0468x; 1.0468x over previous
#include <cuda_runtime.h>
#include <cstdint>

namespace {
constexpr int  CIN  = 16;
constexpr int  COUT = 16;
constexpr int  KS   = 4;
constexpr long long NN = 524288;
constexpr int  THREADS = 128;                 // 4 warps
constexpr int  TOK     = 128;                 // tokens per CTA-iter
constexpr int  TILES   = (int)(8 * NN / TOK); // 32768
constexpr int  GRID    = 8192;                // 4 tiles per CTA
constexpr int  PX      = 136;                 // u32 pitch, xh/xl rows (8cq+r banks)
constexpr int  PS      = 132;                 // f32 pitch, s rows
}

__device__ __forceinline__ unsigned long long fma2(unsigned long long a,
                                                   unsigned long long b,
                                                   unsigned long long c) {
    unsigned long long d;
    asm("fma.rn.f32x2 %0, %1, %2, %3;" : "=l"(d) : "l"(a), "l"(b), "l"(c));
    return d;
}
__device__ __forceinline__ unsigned long long pack2(float lo, float hi) {
    unsigned long long d;
    asm("mov.b64 %0, {%1, %2};" : "=l"(d) : "f"(lo), "f"(hi));
    return d;
}
// pack two f32 -> bf16x2 rn. First operand = HIGH half (element 1).
__device__ __forceinline__ uint32_t packbf(float hi, float lo) {
    uint32_t r;
    asm("cvt.rn.bf16x2.f32 %0, %1, %2;" : "=r"(r) : "f"(hi), "f"(lo));
    return r;
}
// m16n8k16 row.col bf16 MMA, accumulate in place. A = weights (regs).
__device__ __forceinline__ void mma_bf16(float* d, const uint32_t* a,
                                         uint32_t b0, uint32_t b1) {
    asm volatile(
        "mma.sync.aligned.m16n8k16.row.col.f32.bf16.bf16.f32 "
        "{%0,%1,%2,%3}, {%4,%5,%6,%7}, {%8,%9}, {%0,%1,%2,%3};"
        : "+f"(d[0]), "+f"(d[1]), "+f"(d[2]), "+f"(d[3])
        : "r"(a[0]), "r"(a[1]), "r"(a[2]), "r"(a[3]), "r"(b0), "r"(b1));
}
__device__ __forceinline__ float u64lo(unsigned long long v) {
    return __uint_as_float((uint32_t)v);
}
__device__ __forceinline__ float u64hi(unsigned long long v) {
    return __uint_as_float((uint32_t)(v >> 32));
}

__global__ __launch_bounds__(THREADS, 5)
void tconv_mma_kernel(const float* __restrict__ inp,   // [B, CIN, N]
                      const float* __restrict__ wgt,   // [COUT, KS, CIN]
                      const float* __restrict__ att,   // [B, KS, N]
                      float* __restrict__ out)         // [B, COUT, N]
{
    // x pre-split into bf16 hi/lo channel-pairs at staging: row = pair (c/2),
    // word t holds bf16x2 (c=2p low, c=2p+1 high) of token t.
    __shared__ __align__(16) uint32_t xh[2][8 * PX];
    __shared__ __align__(16) uint32_t xl[2][8 * PX];
    __shared__ __align__(16) float    ssm[2][KS * PS];   // s full fp32 [k][tok]

    const int tid  = threadIdx.x;
    const int lane = tid & 31;
    const int w    = tid >> 5;
    const int cq   = lane & 3;
    const int r    = lane >> 2;
    const int c0   = tid >> 5;      // staging: pair-group / s-row
    const int q    = lane;          // staging: token slot

    // ---- W as A-fragments, built once (split hi/lo) — identical to R10 ----
    uint32_t ah[KS][4], al[KS][4];
    #pragma unroll
    for (int kt = 0; kt < KS; kt++) {
        #pragma unroll
        for (int idx = 0; idx < 4; idx++) {
            int o  = r + 8 * (idx & 1);
            int cb = 2 * cq + 8 * (idx >> 1);
            float wa = wgt[(o * KS + kt) * CIN + cb];
            float wb = wgt[(o * KS + kt) * CIN + cb + 1];
            uint32_t hp = packbf(wb, wa);
            float ha = __uint_as_float(hp << 16);
            float hb = __uint_as_float(hp & 0xFFFF0000u);
            ah[kt][idx] = hp;
            al[kt][idx] = packbf(wb - hb, wa - ha);
        }
    }

    // ---- prologue: load tile 0 into regs ----
    // x: pairs {c0, c0+4}, rows 2p & 2p+1, token groups {2q, 64+2q} (float2 each)
    float2 ra[2][2], rb[2][2];
    float4 rs;
    {
        int t = blockIdx.x;
        long long b = t >> 12, n0 = ((long long)(t & 4095) << 7);
        #pragma unroll
        for (int pp = 0; pp < 2; pp++) {
            int p = c0 + 4 * pp;
            #pragma unroll
            for (int g = 0; g < 2; g++) {
                long long tk = n0 + 64 * g + 2 * q;
                ra[pp][g] = *reinterpret_cast<const float2*>(inp + (b * CIN + 2 * p)     * NN + tk);
                rb[pp][g] = *reinterpret_cast<const float2*>(inp + (b * CIN + 2 * p + 1) * NN + tk);
            }
        }
        rs = *reinterpret_cast<const float4*>(att + (b * KS + c0) * NN + n0 + 4 * q);
    }

    for (int i = 0; i < TILES / GRID; i++) {
        const int t = blockIdx.x + i * GRID;
        const int pbuf = i & 1;
        uint32_t* xhb = xh[pbuf];
        uint32_t* xlb = xl[pbuf];
        float*    sb  = ssm[pbuf];

        // ---- stage tile i: split x to bf16 hi/lo, write channel-pair words ----
        #pragma unroll
        for (int pp = 0; pp < 2; pp++) {
            int p = c0 + 4 * pp;
            #pragma unroll
            for (int g = 0; g < 2; g++) {
                int t0 = 64 * g + 2 * q;
                float a0 = ra[pp][g].x, b0 = rb[pp][g].x;
                float a1 = ra[pp][g].y, b1 = rb[pp][g].y;
                uint32_t h0 = packbf(b0, a0);
                uint32_t h1 = packbf(b1, a1);
                float f0lo = __uint_as_float(h0 << 16), f0hi = __uint_as_float(h0 & 0xFFFF0000u);
                float f1lo = __uint_as_float(h1 << 16), f1hi = __uint_as_float(h1 & 0xFFFF0000u);
                uint32_t l0 = packbf(b0 - f0hi, a0 - f0lo);
                uint32_t l1 = packbf(b1 - f1hi, a1 - f1lo);
                *reinterpret_cast<uint2*>(xhb + p * PX + t0) = make_uint2(h0, h1);
                *reinterpret_cast<uint2*>(xlb + p * PX + t0) = make_uint2(l0, l1);
            }
        }
        *reinterpret_cast<float4*>(sb + c0 * PS + 4 * q) = rs;

        // prefetch tile i+1 before the barrier
        if (i + 1 < TILES / GRID) {
            int tn = t + GRID;
            long long b = tn >> 12, n0 = ((long long)(tn & 4095) << 7);
            #pragma unroll
            for (int pp = 0; pp < 2; pp++) {
                int p = c0 + 4 * pp;
                #pragma unroll
                for (int g = 0; g < 2; g++) {
                    long long tk = n0 + 64 * g + 2 * q;
                    ra[pp][g] = *reinterpret_cast<const float2*>(inp + (b * CIN + 2 * p)     * NN + tk);
                    rb[pp][g] = *reinterpret_cast<const float2*>(inp + (b * CIN + 2 * p + 1) * NN + tk);
                }
            }
            rs = *reinterpret_cast<const float4*>(att + (b * KS + c0) * NN + n0 + 4 * q);
        }
        __syncthreads();

        const long long bb = t >> 12;
        const long long n0 = ((long long)(t & 4095) << 7);
        float* ob = out + bb * COUT * NN + n0;

        #pragma unroll
        for (int jp = 0; jp < 2; jp++) {
            const int tb0 = w * 32 + jp * 16;
            const int tb1 = tb0 + 8;
            unsigned long long yA0, yA1, yB0, yB1;   // row r / r+8 token-pairs

            // ===== n8 tile A (tokens tb0..tb0+7) =====
            {
                const int tA = tb0 + r;
                uint32_t bh0 = xhb[cq * PX + tA];
                uint32_t bh1 = xhb[(cq + 4) * PX + tA];
                uint32_t bl0 = xlb[cq * PX + tA];
                uint32_t bl1 = xlb[(cq + 4) * PX + tA];
                float dG[KS][4] = {};
                #pragma unroll
                for (int kt = 0; kt < KS; kt++) {
                    mma_bf16(dG[kt], ah[kt], bh0, bh1);
                    mma_bf16(dG[kt], ah[kt], bl0, bl1);
                    mma_bf16(dG[kt], al[kt], bh0, bh1);
                }
                yA0 = 0ull; yA1 = 0ull;
                #pragma unroll
                for (int kt = 0; kt < KS; kt++) {
                    unsigned long long s2 = *reinterpret_cast<const unsigned long long*>(
                        sb + kt * PS + tb0 + 2 * cq);
                    yA0 = fma2(pack2(dG[kt][0], dG[kt][1]), s2, yA0);
                    yA1 = fma2(pack2(dG[kt][2], dG[kt][3]), s2, yA1);
                }
            }
            // ===== n8 tile B (tokens tb1..tb1+7) =====
            {
                const int tB = tb1 + r;
                uint32_t bh0 = xhb[cq * PX + tB];
                uint32_t bh1 = xhb[(cq + 4) * PX + tB];
                uint32_t bl0 = xlb[cq * PX + tB];
                uint32_t bl1 = xlb[(cq + 4) * PX + tB];
                float dG[KS][4] = {};
                #pragma unroll
                for (int kt = 0; kt < KS; kt++) {
                    mma_bf16(dG[kt], ah[kt], bh0, bh1);
                    mma_bf16(dG[kt], ah[kt], bl0, bl1);
                    mma_bf16(dG[kt], al[kt], bh0, bh1);
                }
                yB0 = 0ull; yB1 = 0ull;
                #pragma unroll
                for (int kt = 0; kt < KS; kt++) {
                    unsigned long long s2 = *reinterpret_cast<const unsigned long long*>(
                        sb + kt * PS + tb1 + 2 * cq);
                    yB0 = fma2(pack2(dG[kt][0], dG[kt][1]), s2, yB0);
                    yB1 = fma2(pack2(dG[kt][2], dG[kt][3]), s2, yB1);
                }
            }

            // ===== composed stores (R10's proven mapping, y as u64 pairs) =====
            const unsigned FULL = 0xFFFFFFFFu;
            unsigned long long eA0 = __shfl_xor_sync(FULL, yA0, 1);
            unsigned long long eA1 = __shfl_xor_sync(FULL, yA1, 1);
            unsigned long long eB0 = __shfl_xor_sync(FULL, yB0, 1);
            unsigned long long eB1 = __shfl_xor_sync(FULL, yB1, 1);

            const int off = ((cq & 1) << 3) | ((cq >> 1) << 2);
            float4 v0, v1;
            if ((cq & 1) == 0) {
                v0 = make_float4(u64lo(yA0), u64hi(yA0), u64lo(eA0), u64hi(eA0));
                v1 = make_float4(u64lo(yA1), u64hi(yA1), u64lo(eA1), u64hi(eA1));
            } else {
                v0 = make_float4(u64lo(eB0), u64hi(eB0), u64lo(yB0), u64hi(yB0));
                v1 = make_float4(u64lo(eB1), u64hi(eB1), u64lo(yB1), u64hi(yB1));
            }
            *reinterpret_cast<float4*>(ob + (long long)r       * NN + tb0 + off) = v0;
            *reinterpret_cast<float4*>(ob + (long long)(r + 8) * NN + tb0 + off) = v1;
        }
    }
}

extern "C" void kernel_launch(void* const* d_in, const int* in_sizes, int n_in,
                              void* d_out, int out_size)
{
    const float* inp = (const float*)d_in[0];   // input  [8,16,524288]
    const float* wgt = (const float*)d_in[1];   // weight [16,4,16]
    const float* att = (const float*)d_in[2];   // attention_score [8,4,524288]
    float* out = (float*)d_out;                 // [8,16,524288]

    tconv_mma_kernel<<<GRID, THREADS>>>(inp, wgt, att, out);
}